// round 1
// baseline (speedup 1.0000x reference)
#include <cuda_runtime.h>

// Problem constants (fixed by reference setup_inputs)
#define C_    128
#define D_    24
#define H_    128
#define W_    128
#define HW_   (H_ * W_)
#define DHW_  (D_ * HW_)
#define OUTH  7
#define OUTD  4
#define SN_   2
#define NBINS (OUTD * OUTH * OUTH)   // 196
#define CG    32                     // channels per block (gridDim.y = C_/CG = 4)

#define SCALE_XY 0.125f
#define SCALE_Z  0.25f

__global__ __launch_bounds__(NBINS, 4)
void roialign3d_kernel(const float* __restrict__ feat,
                       const float* __restrict__ rois,
                       float* __restrict__ out,
                       int R)
{
    const int r   = blockIdx.x;          // roi index
    const int cg  = blockIdx.y;          // channel group
    const int bin = threadIdx.x;         // 0..195  (output bin; contiguous out dim)
    const int w   = bin % OUTH;
    const int h   = (bin / OUTH) % OUTH;
    const int d   = bin / (OUTH * OUTH);

    // ---- ROI params (uniform across block) ----
    const float* roi = rois + (size_t)r * 7;
    const int   b  = (int)__ldg(roi + 0);
    const float x1 = __ldg(roi + 1) * SCALE_XY;
    const float y1 = __ldg(roi + 2) * SCALE_XY;
    const float x2 = __ldg(roi + 3) * SCALE_XY;
    const float y2 = __ldg(roi + 4) * SCALE_XY;
    const float z1 = __ldg(roi + 5) * SCALE_Z;
    const float z2 = __ldg(roi + 6) * SCALE_Z;

    const float bw = fmaxf(x2 - x1, 1.0f) * (1.0f / OUTH);
    const float bh = fmaxf(y2 - y1, 1.0f) * (1.0f / OUTH);
    const float bd = fmaxf(z2 - z1, 1.0f) * (1.0f / OUTD);

    // ---- Per-bin sample axis data (computed ONCE, reused for all channels) ----
    // Per axis-sample: base offset, step-to-high (0 if clipped), weights with
    // the validity flag folded in (indices are always clipped in-bounds, so
    // out-of-range samples simply contribute 0).
    int   zoff[SN_], zstep[SN_];
    float zw0[SN_], zw1[SN_];
    int   yoff[SN_], ystep[SN_];
    float yw0[SN_], yw1[SN_];
    int   xoff[SN_], xstep[SN_];
    float xw0[SN_], xw1[SN_];

#pragma unroll
    for (int s = 0; s < SN_; s++) {
        // z axis (dim D_)
        {
            float c  = z1 + ((float)d + 0.25f + 0.5f * (float)s) * bd;
            float v  = (c > -1.0f && c < (float)D_) ? 1.0f : 0.0f;
            float cc = fminf(fmaxf(c, 0.0f), (float)(D_ - 1));
            int   lo = (int)cc;                      // floor, cc >= 0
            float f  = cc - (float)lo;
            zoff[s]  = lo * HW_;
            zstep[s] = (lo < D_ - 1) ? HW_ : 0;
            zw0[s]   = (1.0f - f) * v;
            zw1[s]   = f * v;
        }
        // y axis (dim H_)
        {
            float c  = y1 + ((float)h + 0.25f + 0.5f * (float)s) * bh;
            float v  = (c > -1.0f && c < (float)H_) ? 1.0f : 0.0f;
            float cc = fminf(fmaxf(c, 0.0f), (float)(H_ - 1));
            int   lo = (int)cc;
            float f  = cc - (float)lo;
            yoff[s]  = lo * W_;
            ystep[s] = (lo < H_ - 1) ? W_ : 0;
            yw0[s]   = (1.0f - f) * v;
            yw1[s]   = f * v;
        }
        // x axis (dim W_)
        {
            float c  = x1 + ((float)w + 0.25f + 0.5f * (float)s) * bw;
            float v  = (c > -1.0f && c < (float)W_) ? 1.0f : 0.0f;
            float cc = fminf(fmaxf(c, 0.0f), (float)(W_ - 1));
            int   lo = (int)cc;
            float f  = cc - (float)lo;
            xoff[s]  = lo;
            xstep[s] = (lo < W_ - 1) ? 1 : 0;
            xw0[s]   = (1.0f - f) * v;
            xw1[s]   = f * v;
        }
    }

    // ---- Channel loop: all address/weight math above is reused 32x ----
    const int c0 = cg * CG;
    const float* pbase = feat + ((size_t)b * C_ + c0) * (size_t)DHW_;
    float* obase = out + ((size_t)(r * C_ + c0)) * (size_t)NBINS + bin;

    for (int ci = 0; ci < CG; ci++) {
        const float* p = pbase + (size_t)ci * DHW_;
        float acc = 0.0f;

#pragma unroll
        for (int sz = 0; sz < SN_; sz++) {
            const float* pz = p + zoff[sz];
            const int    dz = zstep[sz];
#pragma unroll
            for (int sy = 0; sy < SN_; sy++) {
                const float* py = pz + yoff[sy];
                const int    dy = ystep[sy];
#pragma unroll
                for (int sx = 0; sx < SN_; sx++) {
                    const float* q = py + xoff[sx];
                    const int    dx = xstep[sx];

                    float v000 = __ldg(q);
                    float v001 = __ldg(q + dx);
                    float v010 = __ldg(q + dy);
                    float v011 = __ldg(q + dy + dx);
                    float v100 = __ldg(q + dz);
                    float v101 = __ldg(q + dz + dx);
                    float v110 = __ldg(q + dz + dy);
                    float v111 = __ldg(q + dz + dy + dx);

                    float a0 = xw0[sx], a1 = xw1[sx];
                    float b0 = yw0[sy], b1 = yw1[sy];
                    float g0 = zw0[sz], g1 = zw1[sz];

                    float t0 = fmaf(a1, v001, a0 * v000);
                    float t1 = fmaf(a1, v011, a0 * v010);
                    float t2 = fmaf(a1, v101, a0 * v100);
                    float t3 = fmaf(a1, v111, a0 * v110);
                    float u0 = fmaf(b1, t1, b0 * t0);
                    float u1 = fmaf(b1, t3, b0 * t2);
                    acc = fmaf(g1, u1, fmaf(g0, u0, acc));
                }
            }
        }

        obase[(size_t)ci * NBINS] = acc * 0.125f;   // mean over SN^3 = 8 samples
    }
}

extern "C" void kernel_launch(void* const* d_in, const int* in_sizes, int n_in,
                              void* d_out, int out_size)
{
    const float* feat = (const float*)d_in[0];
    const float* rois = (const float*)d_in[1];
    float* out = (float*)d_out;

    const int R = in_sizes[1] / 7;   // 256

    dim3 grid(R, C_ / CG, 1);        // 256 x 4
    dim3 block(NBINS, 1, 1);         // 196 threads (7 warps)
    roialign3d_kernel<<<grid, block>>>(feat, rois, out, R);
}